// round 2
// baseline (speedup 1.0000x reference)
#include <cuda_runtime.h>
#include <math.h>

#define B   32
#define LL  128
#define LR  128
#define D   512
#define M   64
#define A   128
#define OC  259   // 1+64 | 64 | 1+64 | 1+64

// ---- scratch (static device globals; no runtime allocation) ----
__device__ float g_algt[(B*LL + B*LR) * A];   // a_lt rows [0,4096) then a_rt rows
__device__ float g_att[B*LL*D];               // attentive context vectors
__device__ float g_invnrt[B*LR];
__device__ int   g_idx[B*LL];

// ============================================================================
// Kernel: a_lt = tanh(L@W1)*diag ; a_rt = tanh(R@W1).  X = [L;R] (8192 x 512).
// grid: 512 blocks x 16 rows, 256 threads.
// ============================================================================
__global__ void __launch_bounds__(256) k_algt(
    const float* __restrict__ Lr, const float* __restrict__ Rr,
    const float* __restrict__ W1, const float* __restrict__ diag)
{
    __shared__ float Xs[16][17];
    __shared__ float Ws[16][A];
    int row0 = blockIdx.x * 16;
    int t = threadIdx.x;
    int c  = t & 127;
    int rh = t >> 7;           // 0/1 -> rows rh*8..rh*8+7
    float acc[8];
    #pragma unroll
    for (int i = 0; i < 8; i++) acc[i] = 0.f;

    for (int kt = 0; kt < D; kt += 16) {
        #pragma unroll
        for (int i = 0; i < 8; i++) {          // 16x128 W1 tile
            int f = i * 256 + t;
            int k = f >> 7, a = f & 127;
            Ws[k][a] = W1[(kt + k) * A + a];
        }
        {                                      // 16x16 X tile
            int r = t >> 4, k = t & 15;
            int grow = row0 + r;
            const float* X = (grow < B*LL) ? (Lr + (size_t)grow * D)
                                           : (Rr + (size_t)(grow - B*LL) * D);
            Xs[r][k] = X[kt + k];
        }
        __syncthreads();
        #pragma unroll
        for (int k = 0; k < 16; k++) {
            float w = Ws[k][c];
            #pragma unroll
            for (int i = 0; i < 8; i++)
                acc[i] = fmaf(Xs[rh*8 + i][k], w, acc[i]);
        }
        __syncthreads();
    }
    #pragma unroll
    for (int i = 0; i < 8; i++) {
        int grow = row0 + rh*8 + i;
        float v = tanhf(acc[i]);
        if (grow < B*LL) v *= diag[c];
        g_algt[(size_t)grow * A + c] = v;
    }
}

// ============================================================================
// Kernel: attentive context.  Per block: (b, 16 l's).
// scores -> softmax -> att = P @ R  -> g_att
// ============================================================================
__global__ void __launch_bounds__(256) k_att(const float* __restrict__ Rr)
{
    __shared__ float alt[16][129];
    __shared__ float art[16][129];
    __shared__ float S[16][132];
    __shared__ __align__(16) float Rs[4 * 512];

    int b  = blockIdx.y;
    int l0 = blockIdx.x * 16;
    int t  = threadIdx.x;
    int li = t >> 4, rj = t & 15;

    #pragma unroll
    for (int i = 0; i < 8; i++) {
        int f = i * 256 + t;
        int r = f >> 7, a = f & 127;
        alt[r][a] = g_algt[(size_t)(b*LL + l0 + r) * A + a];
    }

    for (int rc = 0; rc < 8; rc++) {
        __syncthreads();
        #pragma unroll
        for (int i = 0; i < 8; i++) {
            int f = i * 256 + t;
            int r = f >> 7, a = f & 127;
            art[r][a] = g_algt[(size_t)(B*LL + b*LR + rc*16 + r) * A + a];
        }
        __syncthreads();
        float s = 0.f;
        #pragma unroll 4
        for (int a = 0; a < A; a++) s = fmaf(alt[li][a], art[rj][a], s);
        S[li][rc*16 + rj] = s;
    }
    __syncthreads();

    // softmax rows (8 warps x 2 rows)
    int w = t >> 5, lane = t & 31;
    for (int rr = w; rr < 16; rr += 8) {
        float m0 = -1e30f;
        #pragma unroll
        for (int s0 = 0; s0 < 4; s0++) m0 = fmaxf(m0, S[rr][lane + 32*s0]);
        #pragma unroll
        for (int off = 16; off; off >>= 1) m0 = fmaxf(m0, __shfl_xor_sync(0xffffffffu, m0, off));
        float e[4], sum = 0.f;
        #pragma unroll
        for (int s0 = 0; s0 < 4; s0++) { e[s0] = expf(S[rr][lane + 32*s0] - m0); sum += e[s0]; }
        #pragma unroll
        for (int off = 16; off; off >>= 1) sum += __shfl_xor_sync(0xffffffffu, sum, off);
        float inv = 1.f / sum;
        #pragma unroll
        for (int s0 = 0; s0 < 4; s0++) S[rr][lane + 32*s0] = e[s0] * inv;
    }

    // att = P @ R   (thread owns li, float4 columns dg+16j)
    float4 acc[8];
    #pragma unroll
    for (int j = 0; j < 8; j++) acc[j] = make_float4(0.f, 0.f, 0.f, 0.f);
    int dg = rj;
    for (int rc = 0; rc < 32; rc++) {
        __syncthreads();
        #pragma unroll
        for (int i = 0; i < 8; i++) {
            int f = i * 256 + t;
            int r4 = f >> 9, d = f & 511;
            Rs[r4*512 + d] = Rr[(size_t)(b*LR + rc*4 + r4) * D + d];
        }
        __syncthreads();
        #pragma unroll
        for (int r4 = 0; r4 < 4; r4++) {
            float p = S[li][rc*4 + r4];
            const float4* Rrow = (const float4*)(Rs + r4*512);
            #pragma unroll
            for (int j = 0; j < 8; j++) {
                float4 v = Rrow[dg + 16*j];
                acc[j].x = fmaf(p, v.x, acc[j].x);
                acc[j].y = fmaf(p, v.y, acc[j].y);
                acc[j].z = fmaf(p, v.z, acc[j].z);
                acc[j].w = fmaf(p, v.w, acc[j].w);
            }
        }
    }
    float4* out = (float4*)(g_att + (size_t)(b*LL + l0 + li) * D);
    #pragma unroll
    for (int j = 0; j < 8; j++) out[dg + 16*j] = acc[j];
}

// ============================================================================
// Kernel: inv right norms:  rsqrt(max(||R[b,r]||^2, eps))
// ============================================================================
__global__ void k_nrt(const float* __restrict__ Rr)
{
    int b = blockIdx.x, t = threadIdx.x, w = t >> 5, lane = t & 31;
    for (int r = w; r < LR; r += 8) {
        const float* row = Rr + (size_t)(b*LR + r) * D;
        float s = 0.f;
        #pragma unroll 4
        for (int i = lane; i < D; i += 32) s = fmaf(row[i], row[i], s);
        #pragma unroll
        for (int off = 16; off; off >>= 1) s += __shfl_xor_sync(0xffffffffu, s, off);
        if (!lane) g_invnrt[b*LR + r] = rsqrtf(fmaxf(s, 1e-6f));
    }
}

// ============================================================================
// Kernel: argmax_r cosine(L[l], R[r]) -> g_idx.  n_lt factor drops out.
// Per block: (b, 16 l's). thread = (li, rj).
// ============================================================================
__global__ void __launch_bounds__(256) k_idx(
    const float* __restrict__ Lr, const float* __restrict__ Rr)
{
    __shared__ __align__(16) float Ls[16 * 512];
    __shared__ float Rs[16 * 67];
    int b = blockIdx.y, l0 = blockIdx.x * 16, t = threadIdx.x;

    #pragma unroll
    for (int i = 0; i < 32; i++) {
        int f = i * 256 + t;
        int r = f >> 9, d = f & 511;
        Ls[r*512 + d] = Lr[(size_t)(b*LL + l0 + r) * D + d];
    }

    int li = t >> 4, rj = t & 15;
    float bestv = -1e30f; int bestr = 0;
    for (int rc = 0; rc < 8; rc++) {
        float acc = 0.f;
        for (int dc = 0; dc < 8; dc++) {
            __syncthreads();
            #pragma unroll
            for (int i = 0; i < 4; i++) {
                int f = i * 256 + t;
                int rr = f >> 6, dd = f & 63;
                Rs[rr*67 + dd] = Rr[(size_t)(b*LR + rc*16 + rr) * D + dc*64 + dd];
            }
            __syncthreads();
            #pragma unroll 8
            for (int k = 0; k < 64; k++)
                acc = fmaf(Ls[li*512 + dc*64 + k], Rs[rj*67 + k], acc);
        }
        float rel = acc * g_invnrt[b*LR + rc*16 + rj];
        int r = rc*16 + rj;
        if (rel > bestv) { bestv = rel; bestr = r; }
    }
    // reduce over rj within 16-lane groups; ties -> smaller r (JAX first-occurrence)
    #pragma unroll
    for (int off = 8; off; off >>= 1) {
        float ov = __shfl_down_sync(0xffffffffu, bestv, off, 16);
        int   oi = __shfl_down_sync(0xffffffffu, bestr, off, 16);
        if (ov > bestv || (ov == bestv && oi < bestr)) { bestv = ov; bestr = oi; }
    }
    if (rj == 0) g_idx[b*LL + l0 + li] = bestr;
}

// ============================================================================
// Kernel: generic multi-perspective match.  One block per (b,l), 256 threads.
// mode 0: att = concat(h_rt_fw,h_rt_bw)[b]   (broadcast over l)
// mode 1: att = g_att[b,l]
// mode 2: att = R[b, g_idx[b,l]]
// ============================================================================
__global__ void __launch_bounds__(256) k_mp(
    const float* __restrict__ Lr,
    const float* __restrict__ hfw, const float* __restrict__ hbw,
    const float* __restrict__ Kmat, float* __restrict__ out,
    int mode, int col0, const float* __restrict__ Rr)
{
    __shared__ float prod[512];
    __shared__ float wsum[8];
    int bl = blockIdx.x;                 // b*LL + l
    int b  = bl >> 7;
    int t  = threadIdx.x;
    const float* Lrow = Lr + (size_t)bl * D;

    float p0, p1;
    if (mode == 0) {
        p0 = Lrow[t]       * hfw[b*256 + t];
        p1 = Lrow[t + 256] * hbw[b*256 + t];
    } else if (mode == 1) {
        const float* att = g_att + (size_t)bl * D;
        p0 = Lrow[t] * att[t]; p1 = Lrow[t + 256] * att[t + 256];
    } else {
        const float* att = Rr + (size_t)(b*LR + g_idx[bl]) * D;
        p0 = Lrow[t] * att[t]; p1 = Lrow[t + 256] * att[t + 256];
    }
    prod[t] = p0; prod[t + 256] = p1;

    float s = p0 + p1;
    int w = t >> 5, lane = t & 31;
    #pragma unroll
    for (int off = 16; off; off >>= 1) s += __shfl_xor_sync(0xffffffffu, s, off);
    if (!lane) wsum[w] = s;
    __syncthreads();
    if (t == 0) {
        float c = 0.f;
        #pragma unroll
        for (int i = 0; i < 8; i++) c += wsum[i];
        out[(size_t)bl * OC + col0] = tanhf(c);
    }

    // each warp: 8 perspectives; cache its prod slice in registers
    float pl[16];
    #pragma unroll
    for (int s0 = 0; s0 < 16; s0++) pl[s0] = prod[lane + 32*s0];
    #pragma unroll
    for (int i = 0; i < 8; i++) {
        int m = w*8 + i;
        const float* kr = Kmat + (size_t)m * D;
        float acc = 0.f;
        #pragma unroll
        for (int s0 = 0; s0 < 16; s0++) acc = fmaf(pl[s0], kr[lane + 32*s0], acc);
        #pragma unroll
        for (int off = 16; off; off >>= 1) acc += __shfl_xor_sync(0xffffffffu, acc, off);
        if (!lane) out[(size_t)bl * OC + col0 + 1 + m] = tanhf(acc);
    }
}

// ============================================================================
// Kernel: max-pooling match.  Per block: (m, b) -> 128x128x512 SGEMM
//   C[r,l] = sum_d (R[b,r,d]*K_m[d]) * L[b,l,d];  out = tanh(max_r C[r,l]).
// 256 thr, 8x8 microtile, BK=16.
// ============================================================================
__global__ void __launch_bounds__(256) k_mpool(
    const float* __restrict__ Lr, const float* __restrict__ Rr,
    const float* __restrict__ Kmp, float* __restrict__ out)
{
    __shared__ float Kd[512];
    __shared__ __align__(16) float As[16 * 132];
    __shared__ __align__(16) float Bs[16 * 132];

    int m = blockIdx.x, b = blockIdx.y;
    int t = threadIdx.x;
    int tx = t & 15, ty = t >> 4;

    Kd[t]       = Kmp[(size_t)m * D + t];
    Kd[t + 256] = Kmp[(size_t)m * D + t + 256];

    float acc[8][8];
    #pragma unroll
    for (int i = 0; i < 8; i++)
        #pragma unroll
        for (int j = 0; j < 8; j++) acc[i][j] = 0.f;

    const float* Rb = Rr + (size_t)b * LR * D;
    const float* Lb = Lr + (size_t)b * LL * D;

    for (int d0 = 0; d0 < D; d0 += 16) {
        __syncthreads();
        #pragma unroll
        for (int i = 0; i < 2; i++) {
            int f = i * 256 + t;
            int row = f >> 2, dq = (f & 3) * 4;
            float4 rv = *(const float4*)(Rb + (size_t)row * D + d0 + dq);
            As[(dq + 0) * 132 + row] = rv.x * Kd[d0 + dq + 0];
            As[(dq + 1) * 132 + row] = rv.y * Kd[d0 + dq + 1];
            As[(dq + 2) * 132 + row] = rv.z * Kd[d0 + dq + 2];
            As[(dq + 3) * 132 + row] = rv.w * Kd[d0 + dq + 3];
            float4 lv = *(const float4*)(Lb + (size_t)row * D + d0 + dq);
            Bs[(dq + 0) * 132 + row] = lv.x;
            Bs[(dq + 1) * 132 + row] = lv.y;
            Bs[(dq + 2) * 132 + row] = lv.z;
            Bs[(dq + 3) * 132 + row] = lv.w;
        }
        __syncthreads();
        #pragma unroll
        for (int k = 0; k < 16; k++) {
            float4 a0 = *(const float4*)&As[k*132 + ty*8];
            float4 a1 = *(const float4*)&As[k*132 + ty*8 + 4];
            float4 b0 = *(const float4*)&Bs[k*132 + tx*8];
            float4 b1 = *(const float4*)&Bs[k*132 + tx*8 + 4];
            float av[8] = {a0.x,a0.y,a0.z,a0.w,a1.x,a1.y,a1.z,a1.w};
            float bv[8] = {b0.x,b0.y,b0.z,b0.w,b1.x,b1.y,b1.z,b1.w};
            #pragma unroll
            for (int i = 0; i < 8; i++)
                #pragma unroll
                for (int j = 0; j < 8; j++)
                    acc[i][j] = fmaf(av[i], bv[j], acc[i][j]);
        }
    }

    // max over this thread's 8 r-rows, then over the 16 ty groups via smem
    float cm[8];
    #pragma unroll
    for (int j = 0; j < 8; j++) {
        float v = acc[0][j];
        #pragma unroll
        for (int i = 1; i < 8; i++) v = fmaxf(v, acc[i][j]);
        cm[j] = v;
    }
    __syncthreads();
    #pragma unroll
    for (int j = 0; j < 8; j++) As[ty*132 + tx*8 + j] = cm[j];
    __syncthreads();
    if (t < 128) {
        float v = -1e30f;
        #pragma unroll
        for (int i = 0; i < 16; i++) v = fmaxf(v, As[i*132 + t]);
        out[((size_t)(b*LL + t)) * OC + 65 + m] = tanhf(v);
    }
}

// ============================================================================
extern "C" void kernel_launch(void* const* d_in, const int* in_sizes, int n_in,
                              void* d_out, int out_size)
{
    const float* reps_lt   = (const float*)d_in[0];
    // d_in[1], d_in[2] (h_lt_fw/bw) unused by the reference math
    const float* reps_rt   = (const float*)d_in[3];
    const float* h_rt_fw   = (const float*)d_in[4];
    const float* h_rt_bw   = (const float*)d_in[5];
    const float* k_full    = (const float*)d_in[6];
    const float* k_mpoolW  = (const float*)d_in[7];
    const float* attn_w1   = (const float*)d_in[8];
    const float* diag_w    = (const float*)d_in[9];
    const float* k_attW    = (const float*)d_in[10];
    const float* k_maxattW = (const float*)d_in[11];
    float* out = (float*)d_out;

    // dominant GEMM first
    k_mpool<<<dim3(M, B), 256>>>(reps_lt, reps_rt, k_mpoolW, out);

    // attentive path
    k_algt<<<(B*LL + B*LR) / 16, 256>>>(reps_lt, reps_rt, attn_w1, diag_w);
    k_att<<<dim3(LL/16, B), 256>>>(reps_rt);

    // max-attentive path
    k_nrt<<<B, 256>>>(reps_rt);
    k_idx<<<dim3(LL/16, B), 256>>>(reps_lt, reps_rt);

    // the three mp_match epilogues
    k_mp<<<B*LL, 256>>>(reps_lt, h_rt_fw, h_rt_bw, k_full,    out, 0,   0, reps_rt);
    k_mp<<<B*LL, 256>>>(reps_lt, h_rt_fw, h_rt_bw, k_attW,    out, 1, 129, reps_rt);
    k_mp<<<B*LL, 256>>>(reps_lt, h_rt_fw, h_rt_bw, k_maxattW, out, 2, 194, reps_rt);
}

// round 4
// speedup vs baseline: 1.8952x; 1.8952x over previous
#include <cuda_runtime.h>
#include <math.h>
#include <stdint.h>

#define B   32
#define LL  128
#define LR  128
#define D   512
#define A   128
#define OC  259   // 1+64 | 64 | 1+64 | 1+64

// ---- scratch (static device globals; no runtime allocation) ----
__device__ float g_algt[(B*LL + B*LR) * A];
__device__ float g_att[B*LL*D];
__device__ float g_invnrt[B*LR];
__device__ int   g_idx[B*LL];
// L pre-split to bf16 hi/lo, stored pre-swizzled as (b,chunk) tiles of
// 128 rows x 128B (SW128-style XOR swizzle); chunk = 64 d's.
__device__ __align__(16) unsigned char g_Lh[B*8*16384];
__device__ __align__(16) unsigned char g_Ll[B*8*16384];

__device__ __forceinline__ uint32_t swz(uint32_t x){ return x ^ ((x >> 3) & 0x70u); }
__device__ __forceinline__ uint32_t smem_u32(const void* p){
    uint32_t a;
    asm("{ .reg .u64 t; cvta.to.shared.u64 t, %1; cvt.u32.u64 %0, t; }" : "=r"(a) : "l"(p));
    return a;
}
// split (x0,x1) -> packed bf16x2 hi + packed bf16x2 lo (lo = bf16(x - hi))
__device__ __forceinline__ void split2(float x0, float x1, uint32_t& h, uint32_t& l){
    asm("cvt.rn.bf16x2.f32 %0, %1, %2;" : "=r"(h) : "f"(x1), "f"(x0));
    float h0 = __uint_as_float(h << 16), h1 = __uint_as_float(h & 0xffff0000u);
    asm("cvt.rn.bf16x2.f32 %0, %1, %2;" : "=r"(l) : "f"(x1 - h1), "f"(x0 - h0));
}

#define LDSM4(r0,r1,r2,r3,addr) \
    asm volatile("ldmatrix.sync.aligned.m8n8.x4.shared.b16 {%0,%1,%2,%3}, [%4];" \
        : "=r"(r0),"=r"(r1),"=r"(r2),"=r"(r3) : "r"(addr))

__device__ __forceinline__ void mma_bf16(float* d, const uint32_t* a, const uint32_t* b){
    asm volatile("mma.sync.aligned.m16n8k16.row.col.f32.bf16.bf16.f32 "
        "{%0,%1,%2,%3}, {%4,%5,%6,%7}, {%8,%9}, {%0,%1,%2,%3};"
        : "+f"(d[0]),"+f"(d[1]),"+f"(d[2]),"+f"(d[3])
        : "r"(a[0]),"r"(a[1]),"r"(a[2]),"r"(a[3]), "r"(b[0]),"r"(b[1]));
}

// ============================================================================
// k_split: L (fp32) -> g_Lh/g_Ll bf16 hi/lo swizzled tiles. grid (8, B).
// ============================================================================
__global__ void __launch_bounds__(256) k_split(const float* __restrict__ L)
{
    int c = blockIdx.x, b = blockIdx.y, t = threadIdx.x;
    const float* Lb = L + ((size_t)b << 16) + c*64;
    size_t tile = ((size_t)(b*8 + c)) << 14;
    #pragma unroll
    for (int i = 0; i < 8; i++){
        int f = i*256 + t; int row = f >> 4, q = f & 15;
        float4 v = *(const float4*)(Lb + (size_t)row*512 + q*4);
        uint32_t h01,l01,h23,l23;
        split2(v.x, v.y, h01, l01);
        split2(v.z, v.w, h23, l23);
        uint32_t off = swz((uint32_t)(row*128 + q*8));
        *(uint2*)(g_Lh + tile + off) = make_uint2(h01, h23);
        *(uint2*)(g_Ll + tile + off) = make_uint2(l01, l23);
    }
}

// ============================================================================
// k_mpool_mma: CTA = (m, b).  C[l,r] = sum_d L[l,d]*(R[r,d]*K_m[d]).
// A = L hi/lo (pre-split swizzled tiles), B = (R*K_m) hi/lo built in smem.
// 3-term split bf16 mma.sync (m16n8k16).  out[b,l,65+m] = tanh(max_r C[l,r]).
// 8 warps = 2(l) x 4(r); warp tile 64x32; acc 4x4 mma positions.
// dyn smem: Ah 16K | Al 16K | Bh 16K | Bl 16K | K 2K = 66K
// ============================================================================
__global__ void __launch_bounds__(256, 2) k_mpool_mma(
    const float* __restrict__ Rr, const float* __restrict__ Kmp,
    float* __restrict__ out)
{
    extern __shared__ __align__(16) unsigned char dyn[];
    int m = blockIdx.x, b = blockIdx.y;
    int t = threadIdx.x, wid = t >> 5, lane = t & 31;
    uint32_t base = smem_u32(dyn);
    uint32_t Ah = base, Al = base + 16384, Bh = base + 32768, Bl = base + 49152;
    float* sK = (float*)(dyn + 65536);
    for (int i = t; i < 512; i += 256) sK[i] = Kmp[(size_t)m*512 + i];
    __syncthreads();

    int wl = wid >> 2, wn = wid & 3;
    float acc[4][4][4];
    #pragma unroll
    for (int i = 0; i < 4; i++)
        #pragma unroll
        for (int j = 0; j < 4; j++)
            #pragma unroll
            for (int k = 0; k < 4; k++) acc[i][j][k] = 0.f;

    // ldmatrix lane addressing
    int rowA = lane & 15;              // rows 0-15 of the 16x16 A subtile
    int cbA  = lane >> 4;              // k-halfblock (16B)
    int rowB = ((lane >> 4) & 1) * 8 + (lane & 7);  // row within n-subtile pair
    int cbB  = (lane >> 3) & 1;        // k-halfblock

    const float* Rb = Rr + ((size_t)b << 16);

    for (int c = 0; c < 8; c++){
        // copy pre-swizzled A tiles (hi/lo), 16KB each
        const uint4* sh = (const uint4*)(g_Lh + (((size_t)(b*8 + c)) << 14));
        const uint4* sl = (const uint4*)(g_Ll + (((size_t)(b*8 + c)) << 14));
        uint4* dh = (uint4*)dyn;
        uint4* dl = (uint4*)(dyn + 16384);
        #pragma unroll
        for (int i = 0; i < 4; i++){ dh[i*256 + t] = sh[i*256 + t]; dl[i*256 + t] = sl[i*256 + t]; }
        // build B = (R*K_m) hi/lo, swizzled
        #pragma unroll
        for (int i = 0; i < 8; i++){
            int f = i*256 + t; int row = f >> 4, q = f & 15;
            float4 rv = *(const float4*)(Rb + (size_t)row*512 + c*64 + q*4);
            float4 k4 = *(const float4*)(sK + c*64 + q*4);
            uint32_t h01,l01,h23,l23;
            split2(rv.x*k4.x, rv.y*k4.y, h01, l01);
            split2(rv.z*k4.z, rv.w*k4.w, h23, l23);
            uint32_t off = swz((uint32_t)(row*128 + q*8));
            asm volatile("st.shared.v2.b32 [%0], {%1,%2};" :: "r"(Bh+off), "r"(h01), "r"(h23));
            asm volatile("st.shared.v2.b32 [%0], {%1,%2};" :: "r"(Bl+off), "r"(l01), "r"(l23));
        }
        __syncthreads();
        #pragma unroll
        for (int ks = 0; ks < 4; ks++){
            uint32_t aoffs[4], boffs[2];
            #pragma unroll
            for (int mt = 0; mt < 4; mt++)
                aoffs[mt] = swz((uint32_t)((wl*64 + mt*16 + rowA)*128 + ks*32 + cbA*16));
            #pragma unroll
            for (int jp = 0; jp < 2; jp++)
                boffs[jp] = swz((uint32_t)((wn*32 + jp*16 + rowB)*128 + ks*32 + cbB*16));

            uint32_t bh_[4][2];
            #pragma unroll
            for (int jp = 0; jp < 2; jp++)
                LDSM4(bh_[jp*2][0], bh_[jp*2][1], bh_[jp*2+1][0], bh_[jp*2+1][1], Bh + boffs[jp]);
            {   // AlBh
                uint32_t al_[4][4];
                #pragma unroll
                for (int mt = 0; mt < 4; mt++)
                    LDSM4(al_[mt][0], al_[mt][1], al_[mt][2], al_[mt][3], Al + aoffs[mt]);
                #pragma unroll
                for (int mt = 0; mt < 4; mt++)
                    #pragma unroll
                    for (int nt = 0; nt < 4; nt++)
                        mma_bf16(acc[mt][nt], al_[mt], bh_[nt]);
            }
            uint32_t ah_[4][4];
            #pragma unroll
            for (int mt = 0; mt < 4; mt++)
                LDSM4(ah_[mt][0], ah_[mt][1], ah_[mt][2], ah_[mt][3], Ah + aoffs[mt]);
            #pragma unroll
            for (int mt = 0; mt < 4; mt++)
                #pragma unroll
                for (int nt = 0; nt < 4; nt++)
                    mma_bf16(acc[mt][nt], ah_[mt], bh_[nt]);
            {   // AhBl
                uint32_t bl_[4][2];
                #pragma unroll
                for (int jp = 0; jp < 2; jp++)
                    LDSM4(bl_[jp*2][0], bl_[jp*2][1], bl_[jp*2+1][0], bl_[jp*2+1][1], Bl + boffs[jp]);
                #pragma unroll
                for (int mt = 0; mt < 4; mt++)
                    #pragma unroll
                    for (int nt = 0; nt < 4; nt++)
                        mma_bf16(acc[mt][nt], ah_[mt], bl_[nt]);
            }
        }
        __syncthreads();
    }

    // epilogue: max over r.  acc rows: l = wl*64+mt*16+g (c0,c1) and +8 (c2,c3);
    // cols: r = wn*32 + nt*8 + tg*2 + {0,1}
    float* red = (float*)dyn;   // 128 x 4
    int g = lane >> 2, tg = lane & 3;
    #pragma unroll
    for (int mt = 0; mt < 4; mt++){
        float m0 = -1e30f, m1 = -1e30f;
        #pragma unroll
        for (int nt = 0; nt < 4; nt++){
            m0 = fmaxf(m0, fmaxf(acc[mt][nt][0], acc[mt][nt][1]));
            m1 = fmaxf(m1, fmaxf(acc[mt][nt][2], acc[mt][nt][3]));
        }
        m0 = fmaxf(m0, __shfl_xor_sync(0xffffffffu, m0, 1));
        m0 = fmaxf(m0, __shfl_xor_sync(0xffffffffu, m0, 2));
        m1 = fmaxf(m1, __shfl_xor_sync(0xffffffffu, m1, 1));
        m1 = fmaxf(m1, __shfl_xor_sync(0xffffffffu, m1, 2));
        if (tg == 0){
            red[(wl*64 + mt*16 + g)*4 + wn]     = m0;
            red[(wl*64 + mt*16 + g + 8)*4 + wn] = m1;
        }
    }
    __syncthreads();
    if (t < 128){
        float v = fmaxf(fmaxf(red[t*4], red[t*4+1]), fmaxf(red[t*4+2], red[t*4+3]));
        out[((size_t)(b*LL + t))*OC + 65 + m] = tanhf(v);
    }
}

// ============================================================================
// k_algt: a_lt = tanh(L@W1)*diag ; a_rt = tanh(R@W1).
// ============================================================================
__global__ void __launch_bounds__(256) k_algt(
    const float* __restrict__ Lr, const float* __restrict__ Rr,
    const float* __restrict__ W1, const float* __restrict__ diag)
{
    __shared__ float Xs[16][17];
    __shared__ float Ws[16][A];
    int row0 = blockIdx.x * 16;
    int t = threadIdx.x;
    int c  = t & 127;
    int rh = t >> 7;
    float acc[8];
    #pragma unroll
    for (int i = 0; i < 8; i++) acc[i] = 0.f;

    for (int kt = 0; kt < D; kt += 16) {
        #pragma unroll
        for (int i = 0; i < 8; i++) {
            int f = i * 256 + t;
            int k = f >> 7, a = f & 127;
            Ws[k][a] = W1[(kt + k) * A + a];
        }
        {
            int r = t >> 4, k = t & 15;
            int grow = row0 + r;
            const float* X = (grow < B*LL) ? (Lr + (size_t)grow * D)
                                           : (Rr + (size_t)(grow - B*LL) * D);
            Xs[r][k] = X[kt + k];
        }
        __syncthreads();
        #pragma unroll
        for (int k = 0; k < 16; k++) {
            float w = Ws[k][c];
            #pragma unroll
            for (int i = 0; i < 8; i++)
                acc[i] = fmaf(Xs[rh*8 + i][k], w, acc[i]);
        }
        __syncthreads();
    }
    #pragma unroll
    for (int i = 0; i < 8; i++) {
        int grow = row0 + rh*8 + i;
        float v = tanhf(acc[i]);
        if (grow < B*LL) v *= diag[c];
        g_algt[(size_t)grow * A + c] = v;
    }
}

// ============================================================================
// k_att: scores -> softmax -> att = P @ R
// ============================================================================
__global__ void __launch_bounds__(256) k_att(const float* __restrict__ Rr)
{
    __shared__ float alt[16][129];
    __shared__ float art[16][129];
    __shared__ float S[16][132];
    __shared__ __align__(16) float Rs[4 * 512];

    int b  = blockIdx.y;
    int l0 = blockIdx.x * 16;
    int t  = threadIdx.x;
    int li = t >> 4, rj = t & 15;

    #pragma unroll
    for (int i = 0; i < 8; i++) {
        int f = i * 256 + t;
        int r = f >> 7, a = f & 127;
        alt[r][a] = g_algt[(size_t)(b*LL + l0 + r) * A + a];
    }

    for (int rc = 0; rc < 8; rc++) {
        __syncthreads();
        #pragma unroll
        for (int i = 0; i < 8; i++) {
            int f = i * 256 + t;
            int r = f >> 7, a = f & 127;
            art[r][a] = g_algt[(size_t)(B*LL + b*LR + rc*16 + r) * A + a];
        }
        __syncthreads();
        float s = 0.f;
        #pragma unroll 4
        for (int a = 0; a < A; a++) s = fmaf(alt[li][a], art[rj][a], s);
        S[li][rc*16 + rj] = s;
    }
    __syncthreads();

    int w = t >> 5, lane = t & 31;
    for (int rr = w; rr < 16; rr += 8) {
        float m0 = -1e30f;
        #pragma unroll
        for (int s0 = 0; s0 < 4; s0++) m0 = fmaxf(m0, S[rr][lane + 32*s0]);
        #pragma unroll
        for (int off = 16; off; off >>= 1) m0 = fmaxf(m0, __shfl_xor_sync(0xffffffffu, m0, off));
        float e[4], sum = 0.f;
        #pragma unroll
        for (int s0 = 0; s0 < 4; s0++) { e[s0] = expf(S[rr][lane + 32*s0] - m0); sum += e[s0]; }
        #pragma unroll
        for (int off = 16; off; off >>= 1) sum += __shfl_xor_sync(0xffffffffu, sum, off);
        float inv = 1.f / sum;
        #pragma unroll
        for (int s0 = 0; s0 < 4; s0++) S[rr][lane + 32*s0] = e[s0] * inv;
    }

    float4 acc[8];
    #pragma unroll
    for (int j = 0; j < 8; j++) acc[j] = make_float4(0.f, 0.f, 0.f, 0.f);
    int dg = rj;
    for (int rc = 0; rc < 32; rc++) {
        __syncthreads();
        #pragma unroll
        for (int i = 0; i < 8; i++) {
            int f = i * 256 + t;
            int r4 = f >> 9, d = f & 511;
            Rs[r4*512 + d] = Rr[(size_t)(b*LR + rc*4 + r4) * D + d];
        }
        __syncthreads();
        #pragma unroll
        for (int r4 = 0; r4 < 4; r4++) {
            float p = S[li][rc*4 + r4];
            const float4* Rrow = (const float4*)(Rs + r4*512);
            #pragma unroll
            for (int j = 0; j < 8; j++) {
                float4 v = Rrow[dg + 16*j];
                acc[j].x = fmaf(p, v.x, acc[j].x);
                acc[j].y = fmaf(p, v.y, acc[j].y);
                acc[j].z = fmaf(p, v.z, acc[j].z);
                acc[j].w = fmaf(p, v.w, acc[j].w);
            }
        }
    }
    float4* outp = (float4*)(g_att + (size_t)(b*LL + l0 + li) * D);
    #pragma unroll
    for (int j = 0; j < 8; j++) outp[dg + 16*j] = acc[j];
}

// ============================================================================
// k_nrt: inv right norms, grid 512 (one warp per row)
// ============================================================================
__global__ void k_nrt(const float* __restrict__ Rr)
{
    int blk = blockIdx.x;
    int b = blk >> 4, r = (blk & 15)*8 + (threadIdx.x >> 5);
    int lane = threadIdx.x & 31;
    const float* row = Rr + (size_t)(b*LR + r) * D;
    float s = 0.f;
    #pragma unroll 4
    for (int i = lane; i < D; i += 32){ float v = row[i]; s = fmaf(v, v, s); }
    #pragma unroll
    for (int off = 16; off; off >>= 1) s += __shfl_xor_sync(0xffffffffu, s, off);
    if (!lane) g_invnrt[b*LR + r] = rsqrtf(fmaxf(s, 1e-6f));
}

// ============================================================================
// k_idx: argmax_r cosine(L[l], R[r])
// ============================================================================
__global__ void __launch_bounds__(256) k_idx(
    const float* __restrict__ Lr, const float* __restrict__ Rr)
{
    __shared__ __align__(16) float Ls[16 * 512];
    __shared__ float Rs[16 * 67];
    int b = blockIdx.y, l0 = blockIdx.x * 16, t = threadIdx.x;

    #pragma unroll
    for (int i = 0; i < 32; i++) {
        int f = i * 256 + t;
        int r = f >> 9, d = f & 511;
        Ls[r*512 + d] = Lr[(size_t)(b*LL + l0 + r) * D + d];
    }

    int li = t >> 4, rj = t & 15;
    float bestv = -1e30f; int bestr = 0;
    for (int rc = 0; rc < 8; rc++) {
        float acc = 0.f;
        for (int dc = 0; dc < 8; dc++) {
            __syncthreads();
            #pragma unroll
            for (int i = 0; i < 4; i++) {
                int f = i * 256 + t;
                int rr = f >> 6, dd = f & 63;
                Rs[rr*67 + dd] = Rr[(size_t)(b*LR + rc*16 + rr) * D + dc*64 + dd];
            }
            __syncthreads();
            #pragma unroll 8
            for (int k = 0; k < 64; k++)
                acc = fmaf(Ls[li*512 + dc*64 + k], Rs[rj*67 + k], acc);
        }
        float rel = acc * g_invnrt[b*LR + rc*16 + rj];
        int r = rc*16 + rj;
        if (rel > bestv) { bestv = rel; bestr = r; }
    }
    #pragma unroll
    for (int off = 8; off; off >>= 1) {
        float ov = __shfl_down_sync(0xffffffffu, bestv, off, 16);
        int   oi = __shfl_down_sync(0xffffffffu, bestr, off, 16);
        if (ov > bestv || (ov == bestv && oi < bestr)) { bestv = ov; bestr = oi; }
    }
    if (rj == 0) g_idx[b*LL + l0 + li] = bestr;
}

// ============================================================================
// k_mp3: all three mp_match epilogues.  grid (256, 3); block = 16 (b,l) rows.
// mode 0: att = h_rt (broadcast); mode 1: g_att; mode 2: R[g_idx].
// ============================================================================
__global__ void __launch_bounds__(256) k_mp3(
    const float* __restrict__ Lr, const float* __restrict__ hfw,
    const float* __restrict__ hbw, const float* __restrict__ Kf,
    const float* __restrict__ Ka, const float* __restrict__ Km,
    const float* __restrict__ Rr, float* __restrict__ out)
{
    __shared__ __align__(16) float P[16][68];
    __shared__ __align__(16) float Kc[64][68];
    __shared__ float hv[512];
    __shared__ float red[16][65];
    __shared__ int   sidx[16];

    int blk = blockIdx.x, mode = blockIdx.y;
    int b = blk >> 3, l0 = (blk & 7) * 16;
    int t = threadIdx.x;
    const float* Kmat = (mode == 0) ? Kf : ((mode == 1) ? Ka : Km);
    int col0 = (mode == 0) ? 0 : ((mode == 1) ? 129 : 194);

    if (mode == 0) { hv[t] = hfw[b*256 + t]; hv[256 + t] = hbw[b*256 + t]; }
    if (mode == 2 && t < 16) sidx[t] = g_idx[b*LL + l0 + t];

    int li = t >> 4, mj = t & 15;
    int srow = t >> 6, sk = t & 63;
    float cacc[4] = {0.f, 0.f, 0.f, 0.f};
    float acc[4]  = {0.f, 0.f, 0.f, 0.f};
    __syncthreads();

    for (int c = 0; c < 8; c++) {
        #pragma unroll
        for (int i = 0; i < 16; i++) {
            int f = i * 256 + t; int m = f >> 6, k = f & 63;
            Kc[m][k] = Kmat[(size_t)m * D + c*64 + k];
        }
        #pragma unroll
        for (int i = 0; i < 4; i++) {
            int row = i*4 + srow;
            int gl = b*LL + l0 + row;
            float lv = Lr[(size_t)gl * D + c*64 + sk];
            float av;
            if (mode == 0)      av = hv[c*64 + sk];
            else if (mode == 1) av = g_att[(size_t)gl * D + c*64 + sk];
            else                av = Rr[(size_t)(b*LR + sidx[row]) * D + c*64 + sk];
            float p = lv * av;
            P[row][sk] = p;
            cacc[i] += p;
        }
        __syncthreads();
        #pragma unroll
        for (int k4 = 0; k4 < 16; k4++) {
            float4 p4 = *(const float4*)&P[li][k4*4];
            #pragma unroll
            for (int j = 0; j < 4; j++) {
                float4 kv = *(const float4*)&Kc[j*16 + mj][k4*4];
                acc[j] = fmaf(p4.x, kv.x, fmaf(p4.y, kv.y, fmaf(p4.z, kv.z, fmaf(p4.w, kv.w, acc[j]))));
            }
        }
        __syncthreads();
    }
    #pragma unroll
    for (int i = 0; i < 4; i++) red[i*4 + srow][sk] = cacc[i];
    __syncthreads();
    if (t < 16) {
        float s = 0.f;
        #pragma unroll
        for (int k = 0; k < 64; k++) s += red[t][k];
        out[(size_t)(b*LL + l0 + t) * OC + col0] = tanhf(s);
    }
    #pragma unroll
    for (int j = 0; j < 4; j++)
        out[(size_t)(b*LL + l0 + li) * OC + col0 + 1 + j*16 + mj] = tanhf(acc[j]);
}

// ============================================================================
extern "C" void kernel_launch(void* const* d_in, const int* in_sizes, int n_in,
                              void* d_out, int out_size)
{
    const float* reps_lt = (const float*)d_in[0];
    const float* reps_rt = (const float*)d_in[3];
    const float* h_rt_fw = (const float*)d_in[4];
    const float* h_rt_bw = (const float*)d_in[5];
    const float* k_full  = (const float*)d_in[6];
    const float* k_mpW   = (const float*)d_in[7];
    const float* attn_w1 = (const float*)d_in[8];
    const float* diag_w  = (const float*)d_in[9];
    const float* k_attW  = (const float*)d_in[10];
    const float* k_maxW  = (const float*)d_in[11];
    float* out = (float*)d_out;

    static int smem_set = 0;
    if (!smem_set) {
        cudaFuncSetAttribute(k_mpool_mma, cudaFuncAttributeMaxDynamicSharedMemorySize, 67584);
        smem_set = 1;
    }

    k_split<<<dim3(8, B), 256>>>(reps_lt);
    k_mpool_mma<<<dim3(64, B), 256, 67584>>>(reps_rt, k_mpW, out);

    k_algt<<<(B*LL + B*LR)/16, 256>>>(reps_lt, reps_rt, attn_w1, diag_w);
    k_att<<<dim3(LL/16, B), 256>>>(reps_rt);
    k_nrt<<<512, 256>>>(reps_rt);
    k_idx<<<dim3(LL/16, B), 256>>>(reps_lt, reps_rt);

    k_mp3<<<dim3(256, 3), 256>>>(reps_lt, h_rt_fw, h_rt_bw,
                                 k_full, k_attW, k_maxW, reps_rt, out);
}